// round 1
// baseline (speedup 1.0000x reference)
#include <cuda_runtime.h>
#include <math.h>

#define NN   4096
#define DD   64
#define OO   64
#define TT   4096
#define LEAK 0.8f

#define CAP  576          // padded nz per row (mean ~410, sd ~19 -> 8.6 sd margin)
#define RPC  28           // rows per CTA
#define NCTA 147          // ceil(4096/28)
#define THREADS 512

// ---------------- static device scratch (no allocations allowed) ----------------
__device__ float          g_wvals[(size_t)NN * CAP];   // ~9.4 MB
__device__ unsigned short g_wcols[(size_t)NN * CAP];   // ~4.7 MB
__device__ float          g_xbuf[2][NN];
__device__ __align__(128) unsigned int          g_count;
__device__ __align__(128) volatile unsigned int g_epoch;

// ---------------- kernel 1: compact dense W rows into padded sparse rows --------
__global__ void build_rows(const float* __restrict__ W) {
    int row  = blockIdx.x;          // 4096 blocks, 128 threads
    int tid  = threadIdx.x;
    int lane = tid & 31;
    int wid  = tid >> 5;
    __shared__ unsigned s_base;
    __shared__ unsigned s_wcnt[4];
    if (tid == 0) s_base = 0;
    __syncthreads();

    const float* wr = W + (size_t)row * NN;
    for (int j0 = 0; j0 < NN; j0 += 128) {
        float v  = wr[j0 + tid];
        bool  nz = (v != 0.0f);
        unsigned ball  = __ballot_sync(0xFFFFFFFFu, nz);
        int      pwarp = __popc(ball & ((1u << lane) - 1u));
        if (lane == 0) s_wcnt[wid] = __popc(ball);
        __syncthreads();
        unsigned wbase = s_base;
        for (int w = 0; w < wid; w++) wbase += s_wcnt[w];
        if (nz) {
            unsigned pos = wbase + (unsigned)pwarp;
            if (pos < CAP) {
                g_wvals[(size_t)row * CAP + pos] = v;
                g_wcols[(size_t)row * CAP + pos] = (unsigned short)(j0 + tid);
            }
        }
        __syncthreads();
        if (tid == 0) s_base += s_wcnt[0] + s_wcnt[1] + s_wcnt[2] + s_wcnt[3];
        __syncthreads();
    }
    // pad remainder with zeros (harmless FMAs at col 0)
    for (unsigned k = s_base + (unsigned)tid; k < CAP; k += 128) {
        g_wvals[(size_t)row * CAP + k] = 0.0f;
        g_wcols[(size_t)row * CAP + k] = 0;
    }
}

// ---------------- kernel 2: init out = bias_out, reset barrier state ------------
__global__ void init_out(float* __restrict__ out, const float* __restrict__ W_out) {
    int i = blockIdx.x * blockDim.x + threadIdx.x;
    if (i == 0) { g_count = 0; g_epoch = 0; }
    if (i < TT * OO) {
        int o = i & 63;
        out[i] = W_out[(size_t)o * (NN + 1) + NN];   // bo[o]
    }
}

// ---------------- kernel 3: persistent recurrence ------------------------------
// smem layout sizes (bytes):
//   s_vals RPC*CAP*4 = 64512
//   s_cols RPC*CAP*2 = 32256
//   s_x    NN*4      = 16384
//   s_Wo   RPC*64*4  = 7168
//   s_Win  RPC*64*4  = 7168
//   s_b    RPC*4     = 112
//   s_xn   RPC*4     = 112
//   s_u    64*4      = 256
#define SMEM_BYTES (RPC*CAP*4 + RPC*CAP*2 + NN*4 + RPC*64*4 + RPC*64*4 + RPC*4 + RPC*4 + 64*4)

__global__ __launch_bounds__(THREADS, 1)
void esn_persistent(const float* __restrict__ inputs,
                    const float* __restrict__ W_in,
                    const float* __restrict__ b,
                    const float* __restrict__ W_out,
                    float* __restrict__ out)
{
    extern __shared__ unsigned char smraw[];
    float*          s_vals = (float*)smraw;
    unsigned short* s_cols = (unsigned short*)(s_vals + RPC * CAP);
    float*          s_x    = (float*)(s_cols + RPC * CAP);
    float*          s_Wo   = s_x + NN;
    float*          s_Win  = s_Wo + RPC * 64;
    float*          s_b    = s_Win + RPC * 64;
    float*          s_xn   = s_b + RPC;
    float*          s_u    = s_xn + RPC;

    const int cta   = blockIdx.x;
    const int tid   = threadIdx.x;
    const int row0  = cta * RPC;
    const int nrows = min(RPC, NN - row0);
    const int lane  = tid & 31;
    const int warp  = tid >> 5;    // 16 warps

    // ---- load per-CTA weight slices into SMEM once ----
    for (int k = tid; k < nrows * CAP; k += THREADS) {
        s_vals[k] = g_wvals[(size_t)row0 * CAP + k];
        s_cols[k] = g_wcols[(size_t)row0 * CAP + k];
    }
    for (int k = tid; k < nrows * 64; k += THREADS) {
        int r = k >> 6, o = k & 63;
        s_Wo[k]  = W_out[(size_t)o * (NN + 1) + row0 + r];
        s_Win[k] = W_in[(size_t)(row0 + r) * DD + o];
    }
    for (int k = tid; k < nrows; k += THREADS) s_b[k] = b[row0 + k];
    for (int k = tid; k < NN; k += THREADS)    s_x[k] = 0.0f;   // x0 = 0
    __syncthreads();

    unsigned epoch = 0;

    for (int t = 0; t < TT; t++) {
        if (tid < 64) s_u[tid] = inputs[(size_t)t * DD + tid];
        __syncthreads();

        const int nb = (t + 1) & 1;   // double-buffer slot being produced

        // ---- recurrent matvec for this CTA's rows (warp per row) ----
        for (int r = warp; r < nrows; r += 16) {
            const float*          rv = s_vals + r * CAP;
            const unsigned short* rc = s_cols + r * CAP;
            float acc = 0.0f;
            #pragma unroll
            for (int k = 0; k < CAP; k += 32)
                acc += rv[k + lane] * s_x[rc[k + lane]];
            // input projection (D=64)
            acc += s_Win[r * 64 + lane]      * s_u[lane];
            acc += s_Win[r * 64 + 32 + lane] * s_u[32 + lane];
            #pragma unroll
            for (int off = 16; off; off >>= 1)
                acc += __shfl_xor_sync(0xFFFFFFFFu, acc, off);
            if (lane == 0) {
                float pre = acc + s_b[r];
                float xo  = s_x[row0 + r];
                float xn  = (1.0f - LEAK) * xo + LEAK * tanhf(pre);
                s_xn[r] = xn;
                __stcg(&g_xbuf[nb][row0 + r], xn);
            }
        }
        __syncthreads();

        // ---- readout partial: y[o] += sum_r Wo[o, row0+r] * xn[r] ----
        if (tid < 64) {
            float y = 0.0f;
            #pragma unroll 4
            for (int r = 0; r < nrows; r++)
                y += s_Wo[r * 64 + tid] * s_xn[r];
            atomicAdd(&out[(size_t)t * OO + tid], y);   // no return use -> RED
        }

        // ---- grid barrier (release g_xbuf writes) ----
        __threadfence();
        __syncthreads();
        if (tid == 0) {
            unsigned old = atomicAdd(&g_count, 1u);
            if (old == NCTA - 1) {
                g_count = 0;
                __threadfence();
                g_epoch = epoch + 1;
            } else {
                while (g_epoch <= epoch) { }
            }
            __threadfence();   // acquire
        }
        __syncthreads();
        epoch++;

        // ---- broadcast-reload full x_{t+1} into SMEM (L2, bypass L1) ----
        for (int k = tid; k < NN; k += THREADS)
            s_x[k] = __ldcg(&g_xbuf[nb][k]);
        __syncthreads();
    }
}

// ---------------- launch ---------------------------------------------------------
extern "C" void kernel_launch(void* const* d_in, const int* in_sizes, int n_in,
                              void* d_out, int out_size) {
    const float* inputs = (const float*)d_in[0];   // (T, D)
    const float* W      = (const float*)d_in[1];   // (N, N)
    const float* W_in   = (const float*)d_in[2];   // (N, D)
    const float* b      = (const float*)d_in[3];   // (N,)
    const float* W_out  = (const float*)d_in[4];   // (O, N+1)
    float* out = (float*)d_out;                    // (T, O) fp32

    cudaFuncSetAttribute(esn_persistent,
                         cudaFuncAttributeMaxDynamicSharedMemorySize, SMEM_BYTES);

    build_rows<<<NN, 128>>>(W);
    init_out<<<(TT * OO + 255) / 256, 256>>>(out, W_out);
    esn_persistent<<<NCTA, THREADS, SMEM_BYTES>>>(inputs, W_in, b, W_out, out);
}

// round 2
// speedup vs baseline: 1.1793x; 1.1793x over previous
#include <cuda_runtime.h>
#include <math.h>

#define NN   4096
#define DD   64
#define OO   64
#define TT   4096
#define LEAK 0.8f

#define NSLOT 24                 // conflict-free slots per bank (mean fill 12.8, +3.4sd)
#define MCAP  (NSLOT * 32)       // 768 elements main region per row
#define TAILC 64                 // spill tail per row (expected total spill ~60 over ALL rows)
#define RPC   28                 // rows per CTA
#define NCTA  147                // ceil(4096/28), 1 CTA/SM -> all co-resident
#define THREADS 896              // 28 warps = warp per row

// ---------------- static device scratch ----------------
__device__ float          g_vals[(size_t)NN * MCAP];    // ~12.6 MB
__device__ unsigned char  g_colh[(size_t)NN * MCAP];    // ~3.1 MB (col>>5, 7 bits)
__device__ float          g_tvals[(size_t)NN * TAILC];  // 1 MB
__device__ unsigned short g_tcols[(size_t)NN * TAILC];  // 0.5 MB
__device__ __align__(16) float g_xbuf[2][NN];
__device__ __align__(128) unsigned int          g_count;
__device__ __align__(128) volatile unsigned int g_epoch;

// ---------------- kernel 1: build bank-slotted sparse rows ----------------
// One warp per row. Lane L owns bank L: scans cols L, L+32, ..., L+32*127
// (each k-iteration the warp reads 128B coalesced). Elements land at
// (slot, bank=L) so that at gather time lane L reads s_x[col] with col%32==L
// -> conflict-free. Bank overflow (slot >= NSLOT) spills to the row tail.
__global__ void build_rows(const float* __restrict__ W) {
    const int lane = threadIdx.x & 31;
    const int row  = blockIdx.x * 8 + (threadIdx.x >> 5);
    const float* wr = W + (size_t)row * NN;
    float*         mv = g_vals + (size_t)row * MCAP;
    unsigned char* mc = g_colh + (size_t)row * MCAP;
    float*          tv = g_tvals + (size_t)row * TAILC;
    unsigned short* tc = g_tcols + (size_t)row * TAILC;

    int cnt = 0;
    for (int k = 0; k < 128; k++) {
        float v = wr[k * 32 + lane];
        if (v != 0.0f) {
            if (cnt < NSLOT) {
                mv[cnt * 32 + lane] = v;
                mc[(cnt >> 2) * 128 + lane * 4 + (cnt & 3)] = (unsigned char)k;
            }
            cnt++;
        }
    }
    // pad empty slots: val=0, colh=0 -> col = lane (still bank-distinct)
    for (int j = (cnt < NSLOT ? cnt : NSLOT); j < NSLOT; j++) {
        mv[j * 32 + lane] = 0.0f;
        mc[(j >> 2) * 128 + lane * 4 + (j & 3)] = 0;
    }
    // zero tail
    for (int j = lane; j < TAILC; j += 32) { tv[j] = 0.0f; tc[j] = 0; }
    __syncwarp();

    int ofl = cnt - NSLOT; if (ofl < 0) ofl = 0;
    if (__ballot_sync(0xFFFFFFFFu, ofl > 0)) {
        int inc = ofl;
        #pragma unroll
        for (int s = 1; s < 32; s <<= 1) {
            int n = __shfl_up_sync(0xFFFFFFFFu, inc, s);
            if (lane >= s) inc += n;
        }
        int wptr = inc - ofl;            // exclusive prefix
        if (ofl > 0) {
            int idx = 0;
            for (int k = 0; k < 128; k++) {
                float v = wr[k * 32 + lane];
                if (v != 0.0f) {
                    if (idx >= NSLOT && wptr < TAILC) {
                        tv[wptr] = v;
                        tc[wptr] = (unsigned short)(k * 32 + lane);
                        wptr++;
                    }
                    idx++;
                }
            }
        }
    }
}

// ---------------- kernel 2: out = bias_out, reset barrier ----------------
__global__ void init_out(float* __restrict__ out, const float* __restrict__ W_out) {
    int i = blockIdx.x * blockDim.x + threadIdx.x;
    if (i == 0) { g_count = 0; g_epoch = 0; }
    if (i < TT * OO) {
        int o = i & 63;
        out[i] = W_out[(size_t)o * (NN + 1) + NN];
    }
}

// ---------------- kernel 3: persistent recurrence ----------------
// smem: s_vals 86016 | s_colh 21504 | s_tvals 7168 | s_tcols 3584 |
//       s_x 16384 | s_Wo 7168 | s_Win 7168 | s_b 128 | s_xn 128 | s_u 256
#define SMEM_BYTES (RPC*MCAP*4 + RPC*MCAP + RPC*TAILC*4 + RPC*TAILC*2 \
                    + NN*4 + RPC*64*4 + RPC*64*4 + 128 + 128 + 256)

__global__ __launch_bounds__(THREADS, 1)
void esn_persistent(const float* __restrict__ inputs,
                    const float* __restrict__ W_in,
                    const float* __restrict__ b,
                    const float* __restrict__ W_out,
                    float* __restrict__ out)
{
    extern __shared__ unsigned char smraw[];
    float*          s_vals  = (float*)smraw;
    unsigned char*  s_colh  = (unsigned char*)(s_vals + RPC * MCAP);
    float*          s_tvals = (float*)(s_colh + RPC * MCAP);
    unsigned short* s_tcols = (unsigned short*)(s_tvals + RPC * TAILC);
    float*          s_x     = (float*)(s_tcols + RPC * TAILC);
    float*          s_Wo    = s_x + NN;
    float*          s_Win   = s_Wo + RPC * 64;
    float*          s_b     = s_Win + RPC * 64;
    float*          s_xn    = s_b + 32;
    float*          s_u     = s_xn + 32;

    const int cta  = blockIdx.x;
    const int tid  = threadIdx.x;
    const int row0 = cta * RPC;
    const int nrows = (NN - row0 < RPC) ? (NN - row0) : RPC;  // 147*28=4116>4096: last CTA has 8
    const int lane = tid & 31;
    const int warp = tid >> 5;          // 0..27 == local row

    // ---- one-time SMEM fill ----
    for (int k = tid; k < nrows * MCAP; k += THREADS) {
        s_vals[k] = g_vals[(size_t)row0 * MCAP + k];
        s_colh[k] = g_colh[(size_t)row0 * MCAP + k];
    }
    for (int k = tid; k < nrows * TAILC; k += THREADS) {
        s_tvals[k] = g_tvals[(size_t)row0 * TAILC + k];
        s_tcols[k] = g_tcols[(size_t)row0 * TAILC + k];
    }
    for (int k = tid; k < nrows * 64; k += THREADS) {
        int r = k >> 6, o = k & 63;
        s_Wo[k]  = W_out[(size_t)o * (NN + 1) + row0 + r];
        s_Win[k] = W_in[(size_t)(row0 + r) * DD + o];
    }
    for (int k = tid; k < 32; k += THREADS) s_b[k] = (k < nrows) ? b[row0 + k] : 0.0f;
    for (int k = tid; k < NN; k += THREADS) s_x[k] = 0.0f;
    if (tid < 64) s_u[tid] = __ldg(&inputs[tid]);
    __syncthreads();

    unsigned epoch = 0;

    for (int t = 0; t < TT; t++) {
        const int nb = (t + 1) & 1;

        // ---- matvec: warp == local row, bank-slotted conflict-free gather ----
        if (warp < nrows) {
            const float*  rv  = s_vals + warp * MCAP;
            const uchar4* rc4 = (const uchar4*)(s_colh + warp * MCAP);
            float acc0 = 0.0f, acc1 = 0.0f;
            #pragma unroll
            for (int sg = 0; sg < NSLOT / 4; sg++) {
                uchar4 c4 = rc4[sg * 32 + lane];
                int j = sg * 4;
                acc0 += rv[(j + 0) * 32 + lane] * s_x[(int)c4.x * 32 + lane];
                acc1 += rv[(j + 1) * 32 + lane] * s_x[(int)c4.y * 32 + lane];
                acc0 += rv[(j + 2) * 32 + lane] * s_x[(int)c4.z * 32 + lane];
                acc1 += rv[(j + 3) * 32 + lane] * s_x[(int)c4.w * 32 + lane];
            }
            const float*          tvp = s_tvals + warp * TAILC;
            const unsigned short* tcp = s_tcols + warp * TAILC;
            #pragma unroll
            for (int c = 0; c < TAILC / 32; c++)
                acc0 += tvp[c * 32 + lane] * s_x[tcp[c * 32 + lane]];
            // input projection (D=64)
            acc0 += s_Win[warp * 64 + lane]      * s_u[lane];
            acc1 += s_Win[warp * 64 + 32 + lane] * s_u[32 + lane];
            float acc = acc0 + acc1;
            #pragma unroll
            for (int off = 16; off; off >>= 1)
                acc += __shfl_xor_sync(0xFFFFFFFFu, acc, off);
            if (lane == 0) {
                float pre = acc + s_b[warp];
                float xn  = (1.0f - LEAK) * s_x[row0 + warp] + LEAK * tanhf(pre);
                s_xn[warp] = xn;
            }
        }
        __syncthreads();

        // ---- publish x_{t+1} slice (coalesced), release ----
        if (tid < nrows) {
            __stcg(&g_xbuf[nb][row0 + tid], s_xn[tid]);
            __threadfence();
        }
        __syncthreads();

        // ---- barrier arrival (early) ----
        if (tid == 0) {
            unsigned old = atomicAdd(&g_count, 1u);
            if (old == NCTA - 1) {
                g_count = 0;
                __threadfence();
                g_epoch = epoch + 1;
            }
        }

        // ---- work in barrier shadow: readout partial + prefetch next u ----
        float u_next = 0.0f;
        if (tid < 64) {
            float y = 0.0f;
            #pragma unroll 7
            for (int r = 0; r < nrows; r++)
                y += s_Wo[r * 64 + tid] * s_xn[r];
            atomicAdd(&out[(size_t)t * OO + tid], y);
            if (t + 1 < TT) u_next = __ldg(&inputs[(size_t)(t + 1) * DD + tid]);
        }

        // ---- barrier wait ----
        if (tid == 0) {
            while (g_epoch <= epoch) { }
            __threadfence();   // acquire
        }
        epoch++;
        __syncthreads();

        // ---- reload full x_{t+1} (L2 broadcast, vectorized) ----
        {
            const float4* src = (const float4*)g_xbuf[nb];
            float4*       dst = (float4*)s_x;
            for (int k = tid; k < NN / 4; k += THREADS)
                dst[k] = __ldcg(src + k);
        }
        if (tid < 64) s_u[tid] = u_next;
        __syncthreads();
    }
}

// ---------------- launch ----------------
extern "C" void kernel_launch(void* const* d_in, const int* in_sizes, int n_in,
                              void* d_out, int out_size) {
    const float* inputs = (const float*)d_in[0];   // (T, D)
    const float* W      = (const float*)d_in[1];   // (N, N)
    const float* W_in   = (const float*)d_in[2];   // (N, D)
    const float* b      = (const float*)d_in[3];   // (N,)
    const float* W_out  = (const float*)d_in[4];   // (O, N+1)
    float* out = (float*)d_out;                    // (T, O)

    cudaFuncSetAttribute(esn_persistent,
                         cudaFuncAttributeMaxDynamicSharedMemorySize, SMEM_BYTES);

    build_rows<<<NN / 8, 256>>>(W);
    init_out<<<(TT * OO + 255) / 256, 256>>>(out, W_out);
    esn_persistent<<<NCTA, THREADS, SMEM_BYTES>>>(inputs, W_in, b, W_out, out);
}